// round 15
// baseline (speedup 1.0000x reference)
#include <cuda_runtime.h>
#include <cuda_bf16.h>
#include <math.h>
#include <stdint.h>

#define A_NUM   9
#define C_NUM   20
#define OUTCH   65
#define BATCH   32
#define KDIM    256
#define HH      56
#define WW      56
#define HW      3136
#define NBOX    64
#define MPOS    2048

// ---- global scratch ----
__device__ __nv_bfloat16 g_w1_hi[KDIM * KDIM];
__device__ __nv_bfloat16 g_w1_lo[KDIM * KDIM];
__device__ __nv_bfloat16 g_w2_hi[OUTCH * KDIM];
__device__ __nv_bfloat16 g_w2_lo[OUTCH * KDIM];
__device__ float         g_out2 [(size_t)BATCH * OUTCH * HW];   // [b][m][p]
__device__ float         g_loss_part[32];

// ---- helpers ----
__device__ __forceinline__ uint32_t smem_u32(const void* p) {
    uint32_t a;
    asm("{ .reg .u64 t; cvta.to.shared.u64 t, %1; cvt.u32.u64 %0, t; }"
        : "=r"(a) : "l"(p));
    return a;
}
__device__ __forceinline__ uint32_t pk2(__nv_bfloat16 a, __nv_bfloat16 b) {
    __nv_bfloat162 t; t.x = a; t.y = b;
    return *(uint32_t*)&t;
}
__device__ __forceinline__ void split1(float x, __nv_bfloat16& h, __nv_bfloat16& l) {
    h = __float2bfloat16(x);
    l = __float2bfloat16(x - __bfloat162float(h));
}
__device__ __forceinline__ void mma16816(float* c,
    const uint32_t* a, uint32_t b0, uint32_t b1)
{
    asm volatile(
        "mma.sync.aligned.m16n8k16.row.col.f32.bf16.bf16.f32 "
        "{%0,%1,%2,%3}, {%4,%5,%6,%7}, {%8,%9}, {%0,%1,%2,%3};"
        : "+f"(c[0]), "+f"(c[1]), "+f"(c[2]), "+f"(c[3])
        : "r"(a[0]), "r"(a[1]), "r"(a[2]), "r"(a[3]), "r"(b0), "r"(b1));
}
__device__ __forceinline__ void ldmx4(uint32_t* r, uint32_t addr) {
    asm volatile("ldmatrix.sync.aligned.m8n8.x4.shared.b16 {%0,%1,%2,%3}, [%4];"
        : "=r"(r[0]), "=r"(r[1]), "=r"(r[2]), "=r"(r[3]) : "r"(addr));
}
__device__ __forceinline__ void ldmx4t(uint32_t* r, uint32_t addr) {
    asm volatile("ldmatrix.sync.aligned.m8n8.x4.trans.shared.b16 {%0,%1,%2,%3}, [%4];"
        : "=r"(r[0]), "=r"(r[1]), "=r"(r[2]), "=r"(r[3]) : "r"(addr));
}
__device__ __forceinline__ void cpa16(uint32_t dst, const void* src, bool ok) {
    uint32_t sz = ok ? 16u : 0u;
    asm volatile("cp.async.cg.shared.global [%0], [%1], 16, %2;"
                 :: "r"(dst), "l"(src), "r"(sz));
}
__device__ __forceinline__ void cpa_commit() {
    asm volatile("cp.async.commit_group;" ::: "memory");
}
__device__ __forceinline__ void cpa_wait1() {
    asm volatile("cp.async.wait_group 1;" ::: "memory");
}
__device__ __forceinline__ void cpa_wait0() {
    asm volatile("cp.async.wait_group 0;" ::: "memory");
}

// ---- SMEM layout ----
#define APITCH    80
#define BPITCH    144
#define ST_STRIDE 49152
#define AHI_OFF   0
#define ALO_OFF   20480
#define BF32_OFF  40960
#define BHI_OFF   98304
#define BLO_OFF   102912
#define HIDHI     0
#define HIDLO     36864
#define W2BASE    73728
#define W2STG     12800
#define GEMM_SMEM 107520     // 2 CTAs/SM (210KB of 228KB)

// ---------------------------------------------------------------------------
__global__ __launch_bounds__(256)
void convert_split(const float* __restrict__ src,
                   __nv_bfloat16* __restrict__ hi,
                   __nv_bfloat16* __restrict__ lo, int n4)
{
    int t = blockIdx.x * blockDim.x + threadIdx.x;
    if (t >= n4) return;
    float4 v = ((const float4*)src)[t];
    __nv_bfloat16 h0, h1, h2, h3, l0, l1, l2, l3;
    split1(v.x, h0, l0); split1(v.y, h1, l1);
    split1(v.z, h2, l2); split1(v.w, h3, l3);
    ((uint2*)hi)[t] = make_uint2(pk2(h0, h1), pk2(h2, h3));
    ((uint2*)lo)[t] = make_uint2(pk2(l0, l1), pk2(l2, l3));
}

// ---------------------------------------------------------------------------
// Fused conv1+conv2 (unchanged from R13-winning version).
// ---------------------------------------------------------------------------
__global__ __launch_bounds__(256, 2)
void gemm_fused(const __nv_bfloat16* __restrict__ Ahi_g,
                const __nv_bfloat16* __restrict__ Alo_g,
                const float* __restrict__ Fraw,
                const float* __restrict__ bias1,
                const __nv_bfloat16* __restrict__ W2hi_g,
                const __nv_bfloat16* __restrict__ W2lo_g,
                const float* __restrict__ bias2)
{
    extern __shared__ char smem[];
    const uint32_t sb = smem_u32(smem);

    const int b     = blockIdx.z;
    const int nBase = blockIdx.x * 64;
    const int tid   = threadIdx.x;
    const int wid   = tid >> 5;
    const int lane  = tid & 31;
    const int wm    = wid >> 1;
    const int wn    = wid & 1;

    const float* fB = Fraw + (size_t)b * KDIM * HW;

    int aOff[4], aDst[4];
    #pragma unroll
    for (int q = 0; q < 4; q++) {
        int e = tid + q * 256, row = e >> 2, c = e & 3;
        aOff[q] = row * KDIM + c * 8;
        aDst[q] = row * APITCH + c * 16;
    }
    int fDst[2];
    size_t fOff[2];
    #pragma unroll
    for (int q = 0; q < 2; q++) {
        int e = tid + q * 256, row = e >> 4, c4 = e & 15;
        fOff[q] = (size_t)row * HW + nBase + c4 * 4;
        fDst[q] = row * 256 + c4 * 16;
    }

    float acc[4][4][4];
    #pragma unroll
    for (int i = 0; i < 4; i++)
        #pragma unroll
        for (int j = 0; j < 4; j++)
            #pragma unroll
            for (int q = 0; q < 4; q++) acc[i][j][q] = 0.f;

    #define ISSUE1(ST, KO)                                                       \
        do {                                                                     \
            _Pragma("unroll")                                                    \
            for (int q = 0; q < 4; q++) {                                        \
                cpa16((ST) + AHI_OFF + aDst[q], Ahi_g + aOff[q] + (KO), true);   \
                cpa16((ST) + ALO_OFF + aDst[q], Alo_g + aOff[q] + (KO), true);   \
            }                                                                    \
            _Pragma("unroll")                                                    \
            for (int q = 0; q < 2; q++)                                          \
                cpa16((ST) + BF32_OFF + fDst[q],                                 \
                      fB + fOff[q] + (size_t)(KO) * HW, true);                   \
        } while (0)

    ISSUE1(sb, 0);
    cpa_commit();
    ISSUE1(sb + ST_STRIDE, 32);
    cpa_commit();

    const int lane15 = lane & 15;
    const int laneHi = lane >> 4;
    const int kB     = (lane >> 3) & 1;
    const int lane7  = lane & 7;
    const uint32_t aFragBase = (wm * 64 + lane15) * APITCH + laneHi * 16;
    const uint32_t bFragRow  = kB * 8 + lane7;
    const uint32_t bFragCol  = (wn * 32 + laneHi * 8) * 2;

    #pragma unroll 1
    for (int c = 0; c < 8; c++) {
        cpa_wait1();
        __syncthreads();
        const uint32_t st = sb + (c & 1) * ST_STRIDE;

        #pragma unroll
        for (int q = 0; q < 2; q++) {
            int e = tid + q * 256, row = e >> 4, c4 = e & 15;
            float4 v = *(const float4*)(smem + (c & 1) * ST_STRIDE + BF32_OFF
                                        + row * 256 + c4 * 16);
            __nv_bfloat16 h0, h1, h2, h3, l0, l1, l2, l3;
            split1(v.x, h0, l0); split1(v.y, h1, l1);
            split1(v.z, h2, l2); split1(v.w, h3, l3);
            *(uint2*)(smem + BHI_OFF + row * BPITCH + c4 * 8) =
                make_uint2(pk2(h0, h1), pk2(h2, h3));
            *(uint2*)(smem + BLO_OFF + row * BPITCH + c4 * 8) =
                make_uint2(pk2(l0, l1), pk2(l2, l3));
        }
        __syncthreads();

        #pragma unroll
        for (int ks = 0; ks < 2; ks++) {
            uint32_t ah[4][4], bh[4][2];
            #pragma unroll
            for (int i = 0; i < 4; i++)
                ldmx4(ah[i], st + AHI_OFF + aFragBase + i * 16 * APITCH + ks * 32);
            {
                uint32_t r[4];
                ldmx4t(r, sb + BHI_OFF + (ks * 16 + bFragRow) * BPITCH + bFragCol);
                bh[0][0] = r[0]; bh[0][1] = r[1]; bh[1][0] = r[2]; bh[1][1] = r[3];
                ldmx4t(r, sb + BHI_OFF + (ks * 16 + bFragRow) * BPITCH + bFragCol + 32);
                bh[2][0] = r[0]; bh[2][1] = r[1]; bh[3][0] = r[2]; bh[3][1] = r[3];
            }
            #pragma unroll
            for (int i = 0; i < 4; i++)
                #pragma unroll
                for (int j = 0; j < 4; j++)
                    mma16816(acc[i][j], ah[i], bh[j][0], bh[j][1]);
            {
                uint32_t bl[4][2], r[4];
                ldmx4t(r, sb + BLO_OFF + (ks * 16 + bFragRow) * BPITCH + bFragCol);
                bl[0][0] = r[0]; bl[0][1] = r[1]; bl[1][0] = r[2]; bl[1][1] = r[3];
                ldmx4t(r, sb + BLO_OFF + (ks * 16 + bFragRow) * BPITCH + bFragCol + 32);
                bl[2][0] = r[0]; bl[2][1] = r[1]; bl[3][0] = r[2]; bl[3][1] = r[3];
                #pragma unroll
                for (int i = 0; i < 4; i++)
                    #pragma unroll
                    for (int j = 0; j < 4; j++)
                        mma16816(acc[i][j], ah[i], bl[j][0], bl[j][1]);
            }
            {
                uint32_t al[4];
                #pragma unroll
                for (int i = 0; i < 4; i++) {
                    ldmx4(al, st + ALO_OFF + aFragBase + i * 16 * APITCH + ks * 32);
                    #pragma unroll
                    for (int j = 0; j < 4; j++)
                        mma16816(acc[i][j], al, bh[j][0], bh[j][1]);
                }
            }
        }
        __syncthreads();
        if (c + 2 < 8) ISSUE1(sb + (c & 1) * ST_STRIDE, (c + 2) * 32);
        cpa_commit();
    }
    #undef ISSUE1

    cpa_wait0();
    __syncthreads();

    const int w2r0 = tid >> 2, w2c0 = tid & 3;
    const int w2r1 = 64 + (tid >> 2), w2c1 = tid & 3;
    const bool w2a1 = tid < 64;
    const bool w2ok1 = w2a1 && (w2r1 < OUTCH);
    const int w2Off0 = w2r0 * KDIM + w2c0 * 8;
    const int w2Off1 = w2ok1 ? (w2r1 * KDIM + w2c1 * 8) : 0;
    const uint32_t w2Dst0 = w2r0 * 80 + w2c0 * 16;
    const uint32_t w2Dst1 = w2r1 * 80 + w2c1 * 16;

    #define ISSUE2(ST, KO)                                                       \
        do {                                                                     \
            cpa16((ST) + w2Dst0,        W2hi_g + w2Off0 + (KO), true);           \
            cpa16((ST) + 6400 + w2Dst0, W2lo_g + w2Off0 + (KO), true);           \
            if (w2a1) {                                                          \
                cpa16((ST) + w2Dst1,        W2hi_g + w2Off1 + (KO), w2ok1);      \
                cpa16((ST) + 6400 + w2Dst1, W2lo_g + w2Off1 + (KO), w2ok1);      \
            }                                                                    \
        } while (0)

    ISSUE2(sb + W2BASE, 0);
    cpa_commit();
    ISSUE2(sb + W2BASE + W2STG, 32);
    cpa_commit();

    const int g   = lane >> 2;
    const int tig = lane & 3;
    #pragma unroll
    for (int i = 0; i < 4; i++) {
        const int m0 = wm * 64 + i * 16 + g;
        const float bv0 = bias1[m0];
        const float bv1 = bias1[m0 + 8];
        #pragma unroll
        for (int j = 0; j < 4; j++) {
            const int p = wn * 32 + j * 8 + tig * 2;
            float f0 = acc[i][j][0] + bv0; f0 = f0 >= 0.f ? f0 : 0.01f * f0;
            float f1 = acc[i][j][1] + bv0; f1 = f1 >= 0.f ? f1 : 0.01f * f1;
            float f2 = acc[i][j][2] + bv1; f2 = f2 >= 0.f ? f2 : 0.01f * f2;
            float f3 = acc[i][j][3] + bv1; f3 = f3 >= 0.f ? f3 : 0.01f * f3;
            __nv_bfloat16 h0, h1, h2, h3, l0, l1, l2, l3;
            split1(f0, h0, l0); split1(f1, h1, l1);
            split1(f2, h2, l2); split1(f3, h3, l3);
            *(uint32_t*)(smem + HIDHI + m0 * BPITCH + p * 2)       = pk2(h0, h1);
            *(uint32_t*)(smem + HIDLO + m0 * BPITCH + p * 2)       = pk2(l0, l1);
            *(uint32_t*)(smem + HIDHI + (m0 + 8) * BPITCH + p * 2) = pk2(h2, h3);
            *(uint32_t*)(smem + HIDLO + (m0 + 8) * BPITCH + p * 2) = pk2(l2, l3);
        }
    }
    __syncthreads();

    const int mw = wid >> 1;
    const int nw = wid & 1;
    const int ibase = (mw == 0) ? 0 : (mw + 1);
    const int icnt  = (mw == 0) ? 2 : 1;

    float acc2[2][4][4];
    #pragma unroll
    for (int ii = 0; ii < 2; ii++)
        #pragma unroll
        for (int j = 0; j < 4; j++)
            #pragma unroll
            for (int q = 0; q < 4; q++) acc2[ii][j][q] = 0.f;

    const uint32_t a2Frag = lane15 * 80 + laneHi * 16;
    const uint32_t b2Col  = (nw * 32 + laneHi * 8) * 2;

    #pragma unroll 1
    for (int c = 0; c < 8; c++) {
        cpa_wait1();
        __syncthreads();
        const uint32_t st = sb + W2BASE + (c & 1) * W2STG;

        #pragma unroll
        for (int ks = 0; ks < 2; ks++) {
            const uint32_t hidRow = (c * 32 + ks * 16 + bFragRow) * BPITCH + b2Col;
            uint32_t bh[4][2], bl[4][2], r[4];
            ldmx4t(r, sb + HIDHI + hidRow);
            bh[0][0] = r[0]; bh[0][1] = r[1]; bh[1][0] = r[2]; bh[1][1] = r[3];
            ldmx4t(r, sb + HIDHI + hidRow + 32);
            bh[2][0] = r[0]; bh[2][1] = r[1]; bh[3][0] = r[2]; bh[3][1] = r[3];
            ldmx4t(r, sb + HIDLO + hidRow);
            bl[0][0] = r[0]; bl[0][1] = r[1]; bl[1][0] = r[2]; bl[1][1] = r[3];
            ldmx4t(r, sb + HIDLO + hidRow + 32);
            bl[2][0] = r[0]; bl[2][1] = r[1]; bl[3][0] = r[2]; bl[3][1] = r[3];

            #pragma unroll
            for (int ii = 0; ii < 2; ii++) {
                if (ii < icnt) {
                    const int i = ibase + ii;
                    uint32_t ah[4], al[4];
                    ldmx4(ah, st + a2Frag + i * 16 * 80 + ks * 32);
                    ldmx4(al, st + 6400 + a2Frag + i * 16 * 80 + ks * 32);
                    #pragma unroll
                    for (int j = 0; j < 4; j++) {
                        mma16816(acc2[ii][j], ah, bh[j][0], bh[j][1]);
                        mma16816(acc2[ii][j], ah, bl[j][0], bl[j][1]);
                        mma16816(acc2[ii][j], al, bh[j][0], bh[j][1]);
                    }
                }
            }
        }
        __syncthreads();
        if (c + 2 < 8) ISSUE2(sb + W2BASE + (c & 1) * W2STG, (c + 2) * 32);
        cpa_commit();
    }
    #undef ISSUE2

    #pragma unroll
    for (int ii = 0; ii < 2; ii++) {
        if (ii < icnt) {
            const int i = ibase + ii;
            const int m0 = i * 16 + g;
            const int m1 = m0 + 8;
            #pragma unroll
            for (int j = 0; j < 4; j++) {
                const int p = nBase + nw * 32 + j * 8 + tig * 2;
                if (m0 < OUTCH) {
                    const float bv = bias2[m0];
                    float2 v = make_float2(acc2[ii][j][0] + bv, acc2[ii][j][1] + bv);
                    *(float2*)&g_out2[((size_t)b * OUTCH + m0) * HW + p] = v;
                }
                if (m1 < OUTCH) {
                    const float bv = bias2[m1];
                    float2 v = make_float2(acc2[ii][j][2] + bv, acc2[ii][j][3] + bv);
                    *(float2*)&g_out2[((size_t)b * OUTCH + m1) * HW + p] = v;
                }
            }
        }
    }
}

// ---------------------------------------------------------------------------
// Head: issue-slot-optimized IoU. Boxes packed as float4 (1 LDS.128/box) +
// ga; fast division (__fdividef = RCP+MUL) replaces ~15-instr IEEE div.
// ---------------------------------------------------------------------------
__global__ __launch_bounds__(256)
void head_kernel(const float* __restrict__ anc,
                 const float* __restrict__ bboxes,
                 float* __restrict__ iou_out)
{
    __shared__ float4 box[NBOX];
    __shared__ float  ga[NBOX];
    const int b = blockIdx.z;
    const int a = blockIdx.y;
    const int tid  = threadIdx.x;
    const int wid  = tid >> 5;
    const int lane = tid & 31;

    if (tid < NBOX) {
        const float* bb = bboxes + ((size_t)b * NBOX + tid) * 5;
        float x1 = bb[0], y1 = bb[1], x2 = bb[2], y2 = bb[3];
        box[tid] = make_float4(x1, y1, x2, y2);
        ga[tid] = (x2 - x1) * (y2 - y1);
    }
    __syncthreads();

    const float wa = anc[a * 2 + 0], ha = anc[a * 2 + 1];
    const float* o = g_out2 + (size_t)b * OUTCH * HW;
    const int pBase = blockIdx.x * 128 + wid * 16;
    const int qmax = (HW - pBase) < 16 ? (HW - pBase) : 16;

    #pragma unroll 2
    for (int q = 0; q < qmax; q++) {
        int p = pBase + q;
        float tx = o[(5 * a + 1) * HW + p];
        float ty = o[(5 * a + 2) * HW + p];
        float tw = o[(5 * a + 3) * HW + p];
        float th = o[(5 * a + 4) * HW + p];
        int h = p / WW, w = p % WW;
        float cx = (w + 0.5f) + tx;
        float cy = (h + 0.5f) + ty;
        float nw = wa * __expf(tw);
        float nh = ha * __expf(th);
        float px1 = cx - nw * 0.5f, px2 = cx + nw * 0.5f;
        float py1 = cy - nh * 0.5f, py2 = cy + nh * 0.5f;
        float parea = (px2 - px1) * (py2 - py1);

        float* orow = iou_out + (((size_t)b * A_NUM + a) * HW + p) * NBOX;
        #pragma unroll
        for (int gg = 0; gg < 2; gg++) {
            int gi = lane + gg * 32;
            float4 bx = box[gi];
            float ix1 = fmaxf(px1, bx.x);
            float iy1 = fmaxf(py1, bx.y);
            float ix2 = fminf(px2, bx.z);
            float iy2 = fminf(py2, bx.w);
            float inter = fmaxf(ix2 - ix1, 0.f) * fmaxf(iy2 - iy1, 0.f);
            orow[gi] = __fdividef(inter, ga[gi] + parea - inter);
        }
    }
}

// ---------------------------------------------------------------------------
__global__ __launch_bounds__(64)
void loss_part(const int* __restrict__ pos_idx,
               const int* __restrict__ neg_idx,
               const float* __restrict__ gt_off)
{
    __shared__ float red[64];
    const int tid = threadIdx.x;
    const int m   = blockIdx.x * 64 + tid;
    float s = 0.f;
    {
        int idx = pos_idx[m];
        int b   = idx / (A_NUM * HW);
        int rem = idx % (A_NUM * HW);
        int a   = rem / HW;
        int p   = rem % HW;
        const float* o = g_out2 + ((size_t)b * OUTCH + 5 * a) * HW + p;
        float c  = o[0];
        float sc = 1.f / (1.f + expf(-c));
        float d  = sc - 1.f;
        s += 0.5f * d * d;
        #pragma unroll
        for (int k = 0; k < 4; k++) {
            float dd = o[(size_t)(1 + k) * HW] - gt_off[m * 4 + k];
            s += dd * dd;
        }
        int nidx = neg_idx[m];
        int nb   = nidx / (A_NUM * HW);
        int nrem = nidx % (A_NUM * HW);
        int na   = nrem / HW;
        int np   = nrem % HW;
        float nc = g_out2[((size_t)nb * OUTCH + 5 * na) * HW + np];
        float nsc = 1.f / (1.f + expf(-nc));
        s += 0.5f * nsc * nsc;
    }
    red[tid] = s;
    __syncthreads();
    for (int st = 32; st > 0; st >>= 1) {
        if (tid < st) red[tid] += red[tid + st];
        __syncthreads();
    }
    if (tid == 0) g_loss_part[blockIdx.x] = red[0];
}

__global__ void loss_final(float* __restrict__ out0)
{
    float s = 0.f;
    #pragma unroll
    for (int i = 0; i < 32; i++) s += g_loss_part[i];
    out0[0] = s / (float)MPOS;
}

// ---------------------------------------------------------------------------
__global__ __launch_bounds__(256)
void class_kernel(const int* __restrict__ pos_idx,
                  float* __restrict__ out_cls)
{
    int t = blockIdx.x * blockDim.x + threadIdx.x;
    if (t >= MPOS * C_NUM) return;
    int m = t / C_NUM;
    int c = t % C_NUM;
    int idx = pos_idx[m];
    int b = idx / (A_NUM * HW);
    int p = idx % HW;
    out_cls[t] = g_out2[((size_t)b * OUTCH + 5 * A_NUM + c) * HW + p];
}

// ---------------------------------------------------------------------------
extern "C" void kernel_launch(void* const* d_in, const int* in_sizes, int n_in,
                              void* d_out, int out_size)
{
    const float* features = (const float*)d_in[0];
    const float* w1       = (const float*)d_in[1];
    const float* b1       = (const float*)d_in[2];
    const float* w2       = (const float*)d_in[3];
    const float* b2       = (const float*)d_in[4];
    const float* anc      = (const float*)d_in[5];
    const float* bboxes   = (const float*)d_in[7];
    const float* gt_off   = (const float*)d_in[8];
    const int*   pos_idx  = (const int*)d_in[9];
    const int*   neg_idx  = (const int*)d_in[10];

    float* out      = (float*)d_out;
    float* loss_out = out;
    float* iou_out  = out + 1;
    float* cls_out  = out + 1 + (size_t)BATCH * A_NUM * HW * NBOX;

    cudaFuncSetAttribute(gemm_fused,
                         cudaFuncAttributeMaxDynamicSharedMemorySize, GEMM_SMEM);

    __nv_bfloat16 *w1h, *w1l, *w2h, *w2l;
    cudaGetSymbolAddress((void**)&w1h, g_w1_hi);
    cudaGetSymbolAddress((void**)&w1l, g_w1_lo);
    cudaGetSymbolAddress((void**)&w2h, g_w2_hi);
    cudaGetSymbolAddress((void**)&w2l, g_w2_lo);

    convert_split<<<(KDIM * KDIM / 4 + 255) / 256, 256>>>(w1, w1h, w1l, KDIM * KDIM / 4);
    convert_split<<<(OUTCH * KDIM / 4 + 255) / 256, 256>>>(w2, w2h, w2l, OUTCH * KDIM / 4);

    gemm_fused<<<dim3(49, 1, BATCH), 256, GEMM_SMEM>>>(w1h, w1l, features, b1,
                                                       w2h, w2l, b2);

    head_kernel<<<dim3(25, A_NUM, BATCH), 256>>>(anc, bboxes, iou_out);
    loss_part<<<32, 64>>>(pos_idx, neg_idx, gt_off);
    loss_final<<<1, 1>>>(loss_out);
    class_kernel<<<(MPOS * C_NUM + 255) / 256, 256>>>(pos_idx, cls_out);
}

// round 16
// speedup vs baseline: 1.0706x; 1.0706x over previous
#include <cuda_runtime.h>
#include <cuda_bf16.h>
#include <math.h>
#include <stdint.h>

#define A_NUM   9
#define C_NUM   20
#define OUTCH   65
#define BATCH   32
#define KDIM    256
#define HH      56
#define WW      56
#define HW      3136
#define NBOX    64
#define MPOS    2048

// ---- global scratch ----
__device__ __nv_bfloat16 g_w1_hi[KDIM * KDIM];
__device__ __nv_bfloat16 g_w1_lo[KDIM * KDIM];
__device__ __nv_bfloat16 g_w2_hi[OUTCH * KDIM];
__device__ __nv_bfloat16 g_w2_lo[OUTCH * KDIM];
__device__ float         g_out2 [(size_t)BATCH * OUTCH * HW];   // [b][m][p]
__device__ float         g_loss_part[32];

// ---- helpers ----
__device__ __forceinline__ uint32_t smem_u32(const void* p) {
    uint32_t a;
    asm("{ .reg .u64 t; cvta.to.shared.u64 t, %1; cvt.u32.u64 %0, t; }"
        : "=r"(a) : "l"(p));
    return a;
}
__device__ __forceinline__ uint32_t pk2(__nv_bfloat16 a, __nv_bfloat16 b) {
    __nv_bfloat162 t; t.x = a; t.y = b;
    return *(uint32_t*)&t;
}
__device__ __forceinline__ void split1(float x, __nv_bfloat16& h, __nv_bfloat16& l) {
    h = __float2bfloat16(x);
    l = __float2bfloat16(x - __bfloat162float(h));
}
__device__ __forceinline__ void mma16816(float* c,
    const uint32_t* a, uint32_t b0, uint32_t b1)
{
    asm volatile(
        "mma.sync.aligned.m16n8k16.row.col.f32.bf16.bf16.f32 "
        "{%0,%1,%2,%3}, {%4,%5,%6,%7}, {%8,%9}, {%0,%1,%2,%3};"
        : "+f"(c[0]), "+f"(c[1]), "+f"(c[2]), "+f"(c[3])
        : "r"(a[0]), "r"(a[1]), "r"(a[2]), "r"(a[3]), "r"(b0), "r"(b1));
}
__device__ __forceinline__ void ldmx4(uint32_t* r, uint32_t addr) {
    asm volatile("ldmatrix.sync.aligned.m8n8.x4.shared.b16 {%0,%1,%2,%3}, [%4];"
        : "=r"(r[0]), "=r"(r[1]), "=r"(r[2]), "=r"(r[3]) : "r"(addr));
}
__device__ __forceinline__ void ldmx4t(uint32_t* r, uint32_t addr) {
    asm volatile("ldmatrix.sync.aligned.m8n8.x4.trans.shared.b16 {%0,%1,%2,%3}, [%4];"
        : "=r"(r[0]), "=r"(r[1]), "=r"(r[2]), "=r"(r[3]) : "r"(addr));
}
__device__ __forceinline__ void cpa16(uint32_t dst, const void* src, bool ok) {
    uint32_t sz = ok ? 16u : 0u;
    asm volatile("cp.async.cg.shared.global [%0], [%1], 16, %2;"
                 :: "r"(dst), "l"(src), "r"(sz));
}
__device__ __forceinline__ void cpa_commit() {
    asm volatile("cp.async.commit_group;" ::: "memory");
}
__device__ __forceinline__ void cpa_wait1() {
    asm volatile("cp.async.wait_group 1;" ::: "memory");
}
__device__ __forceinline__ void cpa_wait0() {
    asm volatile("cp.async.wait_group 0;" ::: "memory");
}

// ---- SMEM layout ----
#define APITCH    80
#define BPITCH    144
#define ST_STRIDE 49152
#define AHI_OFF   0
#define ALO_OFF   20480
#define BF32_OFF  40960
#define BHI_OFF   98304
#define BLO_OFF   102912
#define HIDHI     0
#define HIDLO     36864
#define W2BASE    73728
#define W2STG     12800
#define GEMM_SMEM 107520     // 2 CTAs/SM (210KB of 228KB)

// ---------------------------------------------------------------------------
__global__ __launch_bounds__(256)
void convert_split(const float* __restrict__ src,
                   __nv_bfloat16* __restrict__ hi,
                   __nv_bfloat16* __restrict__ lo, int n4)
{
    int t = blockIdx.x * blockDim.x + threadIdx.x;
    if (t >= n4) return;
    float4 v = ((const float4*)src)[t];
    __nv_bfloat16 h0, h1, h2, h3, l0, l1, l2, l3;
    split1(v.x, h0, l0); split1(v.y, h1, l1);
    split1(v.z, h2, l2); split1(v.w, h3, l3);
    ((uint2*)hi)[t] = make_uint2(pk2(h0, h1), pk2(h2, h3));
    ((uint2*)lo)[t] = make_uint2(pk2(l0, l1), pk2(l2, l3));
}

// ---------------------------------------------------------------------------
// Fused conv1+conv2 (unchanged from R13-winning version).
// ---------------------------------------------------------------------------
__global__ __launch_bounds__(256, 2)
void gemm_fused(const __nv_bfloat16* __restrict__ Ahi_g,
                const __nv_bfloat16* __restrict__ Alo_g,
                const float* __restrict__ Fraw,
                const float* __restrict__ bias1,
                const __nv_bfloat16* __restrict__ W2hi_g,
                const __nv_bfloat16* __restrict__ W2lo_g,
                const float* __restrict__ bias2)
{
    extern __shared__ char smem[];
    const uint32_t sb = smem_u32(smem);

    const int b     = blockIdx.z;
    const int nBase = blockIdx.x * 64;
    const int tid   = threadIdx.x;
    const int wid   = tid >> 5;
    const int lane  = tid & 31;
    const int wm    = wid >> 1;
    const int wn    = wid & 1;

    const float* fB = Fraw + (size_t)b * KDIM * HW;

    int aOff[4], aDst[4];
    #pragma unroll
    for (int q = 0; q < 4; q++) {
        int e = tid + q * 256, row = e >> 2, c = e & 3;
        aOff[q] = row * KDIM + c * 8;
        aDst[q] = row * APITCH + c * 16;
    }
    int fDst[2];
    size_t fOff[2];
    #pragma unroll
    for (int q = 0; q < 2; q++) {
        int e = tid + q * 256, row = e >> 4, c4 = e & 15;
        fOff[q] = (size_t)row * HW + nBase + c4 * 4;
        fDst[q] = row * 256 + c4 * 16;
    }

    float acc[4][4][4];
    #pragma unroll
    for (int i = 0; i < 4; i++)
        #pragma unroll
        for (int j = 0; j < 4; j++)
            #pragma unroll
            for (int q = 0; q < 4; q++) acc[i][j][q] = 0.f;

    #define ISSUE1(ST, KO)                                                       \
        do {                                                                     \
            _Pragma("unroll")                                                    \
            for (int q = 0; q < 4; q++) {                                        \
                cpa16((ST) + AHI_OFF + aDst[q], Ahi_g + aOff[q] + (KO), true);   \
                cpa16((ST) + ALO_OFF + aDst[q], Alo_g + aOff[q] + (KO), true);   \
            }                                                                    \
            _Pragma("unroll")                                                    \
            for (int q = 0; q < 2; q++)                                          \
                cpa16((ST) + BF32_OFF + fDst[q],                                 \
                      fB + fOff[q] + (size_t)(KO) * HW, true);                   \
        } while (0)

    ISSUE1(sb, 0);
    cpa_commit();
    ISSUE1(sb + ST_STRIDE, 32);
    cpa_commit();

    const int lane15 = lane & 15;
    const int laneHi = lane >> 4;
    const int kB     = (lane >> 3) & 1;
    const int lane7  = lane & 7;
    const uint32_t aFragBase = (wm * 64 + lane15) * APITCH + laneHi * 16;
    const uint32_t bFragRow  = kB * 8 + lane7;
    const uint32_t bFragCol  = (wn * 32 + laneHi * 8) * 2;

    #pragma unroll 1
    for (int c = 0; c < 8; c++) {
        cpa_wait1();
        __syncthreads();
        const uint32_t st = sb + (c & 1) * ST_STRIDE;

        #pragma unroll
        for (int q = 0; q < 2; q++) {
            int e = tid + q * 256, row = e >> 4, c4 = e & 15;
            float4 v = *(const float4*)(smem + (c & 1) * ST_STRIDE + BF32_OFF
                                        + row * 256 + c4 * 16);
            __nv_bfloat16 h0, h1, h2, h3, l0, l1, l2, l3;
            split1(v.x, h0, l0); split1(v.y, h1, l1);
            split1(v.z, h2, l2); split1(v.w, h3, l3);
            *(uint2*)(smem + BHI_OFF + row * BPITCH + c4 * 8) =
                make_uint2(pk2(h0, h1), pk2(h2, h3));
            *(uint2*)(smem + BLO_OFF + row * BPITCH + c4 * 8) =
                make_uint2(pk2(l0, l1), pk2(l2, l3));
        }
        __syncthreads();

        #pragma unroll
        for (int ks = 0; ks < 2; ks++) {
            uint32_t ah[4][4], bh[4][2];
            #pragma unroll
            for (int i = 0; i < 4; i++)
                ldmx4(ah[i], st + AHI_OFF + aFragBase + i * 16 * APITCH + ks * 32);
            {
                uint32_t r[4];
                ldmx4t(r, sb + BHI_OFF + (ks * 16 + bFragRow) * BPITCH + bFragCol);
                bh[0][0] = r[0]; bh[0][1] = r[1]; bh[1][0] = r[2]; bh[1][1] = r[3];
                ldmx4t(r, sb + BHI_OFF + (ks * 16 + bFragRow) * BPITCH + bFragCol + 32);
                bh[2][0] = r[0]; bh[2][1] = r[1]; bh[3][0] = r[2]; bh[3][1] = r[3];
            }
            #pragma unroll
            for (int i = 0; i < 4; i++)
                #pragma unroll
                for (int j = 0; j < 4; j++)
                    mma16816(acc[i][j], ah[i], bh[j][0], bh[j][1]);
            {
                uint32_t bl[4][2], r[4];
                ldmx4t(r, sb + BLO_OFF + (ks * 16 + bFragRow) * BPITCH + bFragCol);
                bl[0][0] = r[0]; bl[0][1] = r[1]; bl[1][0] = r[2]; bl[1][1] = r[3];
                ldmx4t(r, sb + BLO_OFF + (ks * 16 + bFragRow) * BPITCH + bFragCol + 32);
                bl[2][0] = r[0]; bl[2][1] = r[1]; bl[3][0] = r[2]; bl[3][1] = r[3];
                #pragma unroll
                for (int i = 0; i < 4; i++)
                    #pragma unroll
                    for (int j = 0; j < 4; j++)
                        mma16816(acc[i][j], ah[i], bl[j][0], bl[j][1]);
            }
            {
                uint32_t al[4];
                #pragma unroll
                for (int i = 0; i < 4; i++) {
                    ldmx4(al, st + ALO_OFF + aFragBase + i * 16 * APITCH + ks * 32);
                    #pragma unroll
                    for (int j = 0; j < 4; j++)
                        mma16816(acc[i][j], al, bh[j][0], bh[j][1]);
                }
            }
        }
        __syncthreads();
        if (c + 2 < 8) ISSUE1(sb + (c & 1) * ST_STRIDE, (c + 2) * 32);
        cpa_commit();
    }
    #undef ISSUE1

    cpa_wait0();
    __syncthreads();

    const int w2r0 = tid >> 2, w2c0 = tid & 3;
    const int w2r1 = 64 + (tid >> 2), w2c1 = tid & 3;
    const bool w2a1 = tid < 64;
    const bool w2ok1 = w2a1 && (w2r1 < OUTCH);
    const int w2Off0 = w2r0 * KDIM + w2c0 * 8;
    const int w2Off1 = w2ok1 ? (w2r1 * KDIM + w2c1 * 8) : 0;
    const uint32_t w2Dst0 = w2r0 * 80 + w2c0 * 16;
    const uint32_t w2Dst1 = w2r1 * 80 + w2c1 * 16;

    #define ISSUE2(ST, KO)                                                       \
        do {                                                                     \
            cpa16((ST) + w2Dst0,        W2hi_g + w2Off0 + (KO), true);           \
            cpa16((ST) + 6400 + w2Dst0, W2lo_g + w2Off0 + (KO), true);           \
            if (w2a1) {                                                          \
                cpa16((ST) + w2Dst1,        W2hi_g + w2Off1 + (KO), w2ok1);      \
                cpa16((ST) + 6400 + w2Dst1, W2lo_g + w2Off1 + (KO), w2ok1);      \
            }                                                                    \
        } while (0)

    ISSUE2(sb + W2BASE, 0);
    cpa_commit();
    ISSUE2(sb + W2BASE + W2STG, 32);
    cpa_commit();

    const int g   = lane >> 2;
    const int tig = lane & 3;
    #pragma unroll
    for (int i = 0; i < 4; i++) {
        const int m0 = wm * 64 + i * 16 + g;
        const float bv0 = bias1[m0];
        const float bv1 = bias1[m0 + 8];
        #pragma unroll
        for (int j = 0; j < 4; j++) {
            const int p = wn * 32 + j * 8 + tig * 2;
            float f0 = acc[i][j][0] + bv0; f0 = f0 >= 0.f ? f0 : 0.01f * f0;
            float f1 = acc[i][j][1] + bv0; f1 = f1 >= 0.f ? f1 : 0.01f * f1;
            float f2 = acc[i][j][2] + bv1; f2 = f2 >= 0.f ? f2 : 0.01f * f2;
            float f3 = acc[i][j][3] + bv1; f3 = f3 >= 0.f ? f3 : 0.01f * f3;
            __nv_bfloat16 h0, h1, h2, h3, l0, l1, l2, l3;
            split1(f0, h0, l0); split1(f1, h1, l1);
            split1(f2, h2, l2); split1(f3, h3, l3);
            *(uint32_t*)(smem + HIDHI + m0 * BPITCH + p * 2)       = pk2(h0, h1);
            *(uint32_t*)(smem + HIDLO + m0 * BPITCH + p * 2)       = pk2(l0, l1);
            *(uint32_t*)(smem + HIDHI + (m0 + 8) * BPITCH + p * 2) = pk2(h2, h3);
            *(uint32_t*)(smem + HIDLO + (m0 + 8) * BPITCH + p * 2) = pk2(l2, l3);
        }
    }
    __syncthreads();

    const int mw = wid >> 1;
    const int nw = wid & 1;
    const int ibase = (mw == 0) ? 0 : (mw + 1);
    const int icnt  = (mw == 0) ? 2 : 1;

    float acc2[2][4][4];
    #pragma unroll
    for (int ii = 0; ii < 2; ii++)
        #pragma unroll
        for (int j = 0; j < 4; j++)
            #pragma unroll
            for (int q = 0; q < 4; q++) acc2[ii][j][q] = 0.f;

    const uint32_t a2Frag = lane15 * 80 + laneHi * 16;
    const uint32_t b2Col  = (nw * 32 + laneHi * 8) * 2;

    #pragma unroll 1
    for (int c = 0; c < 8; c++) {
        cpa_wait1();
        __syncthreads();
        const uint32_t st = sb + W2BASE + (c & 1) * W2STG;

        #pragma unroll
        for (int ks = 0; ks < 2; ks++) {
            const uint32_t hidRow = (c * 32 + ks * 16 + bFragRow) * BPITCH + b2Col;
            uint32_t bh[4][2], bl[4][2], r[4];
            ldmx4t(r, sb + HIDHI + hidRow);
            bh[0][0] = r[0]; bh[0][1] = r[1]; bh[1][0] = r[2]; bh[1][1] = r[3];
            ldmx4t(r, sb + HIDHI + hidRow + 32);
            bh[2][0] = r[0]; bh[2][1] = r[1]; bh[3][0] = r[2]; bh[3][1] = r[3];
            ldmx4t(r, sb + HIDLO + hidRow);
            bl[0][0] = r[0]; bl[0][1] = r[1]; bl[1][0] = r[2]; bl[1][1] = r[3];
            ldmx4t(r, sb + HIDLO + hidRow + 32);
            bl[2][0] = r[0]; bl[2][1] = r[1]; bl[3][0] = r[2]; bl[3][1] = r[3];

            #pragma unroll
            for (int ii = 0; ii < 2; ii++) {
                if (ii < icnt) {
                    const int i = ibase + ii;
                    uint32_t ah[4], al[4];
                    ldmx4(ah, st + a2Frag + i * 16 * 80 + ks * 32);
                    ldmx4(al, st + 6400 + a2Frag + i * 16 * 80 + ks * 32);
                    #pragma unroll
                    for (int j = 0; j < 4; j++) {
                        mma16816(acc2[ii][j], ah, bh[j][0], bh[j][1]);
                        mma16816(acc2[ii][j], ah, bl[j][0], bl[j][1]);
                        mma16816(acc2[ii][j], al, bh[j][0], bh[j][1]);
                    }
                }
            }
        }
        __syncthreads();
        if (c + 2 < 8) ISSUE2(sb + W2BASE + (c & 1) * W2STG, (c + 2) * 32);
        cpa_commit();
    }
    #undef ISSUE2

    #pragma unroll
    for (int ii = 0; ii < 2; ii++) {
        if (ii < icnt) {
            const int i = ibase + ii;
            const int m0 = i * 16 + g;
            const int m1 = m0 + 8;
            #pragma unroll
            for (int j = 0; j < 4; j++) {
                const int p = nBase + nw * 32 + j * 8 + tig * 2;
                if (m0 < OUTCH) {
                    const float bv = bias2[m0];
                    float2 v = make_float2(acc2[ii][j][0] + bv, acc2[ii][j][1] + bv);
                    *(float2*)&g_out2[((size_t)b * OUTCH + m0) * HW + p] = v;
                }
                if (m1 < OUTCH) {
                    const float bv = bias2[m1];
                    float2 v = make_float2(acc2[ii][j][2] + bv, acc2[ii][j][3] + bv);
                    *(float2*)&g_out2[((size_t)b * OUTCH + m1) * HW + p] = v;
                }
            }
        }
    }
}

// ---------------------------------------------------------------------------
// Head: register-hoisted boxes, incremental addressing, guard-free 16-pixel
// strips (HW = 196*16 exactly -> a warp strip is fully valid or fully idle).
// ---------------------------------------------------------------------------
__global__ __launch_bounds__(256)
void head_kernel(const float* __restrict__ anc,
                 const float* __restrict__ bboxes,
                 float* __restrict__ iou_out)
{
    __shared__ float4 box[NBOX];
    __shared__ float  gar[NBOX];
    const int b = blockIdx.z;
    const int a = blockIdx.y;
    const int tid  = threadIdx.x;
    const int wid  = tid >> 5;
    const int lane = tid & 31;

    if (tid < NBOX) {
        const float* bb = bboxes + ((size_t)b * NBOX + tid) * 5;
        float x1 = bb[0], y1 = bb[1], x2 = bb[2], y2 = bb[3];
        box[tid] = make_float4(x1, y1, x2, y2);
        gar[tid] = (x2 - x1) * (y2 - y1);
    }
    __syncthreads();

    const int pBase = blockIdx.x * 128 + wid * 16;
    if (pBase >= HW) return;                 // whole strip out of range

    // hoist this thread's two boxes into registers (invariant over pixels)
    const float4 bx0 = box[lane];
    const float4 bx1 = box[lane + 32];
    const float  ga0 = gar[lane];
    const float  ga1 = gar[lane + 32];

    const float wa = anc[a * 2 + 0], ha = anc[a * 2 + 1];
    const float* o1 = g_out2 + ((size_t)b * OUTCH + 5 * a + 1) * HW + pBase;
    const float* o2 = o1 + HW;
    const float* o3 = o2 + HW;
    const float* o4 = o3 + HW;
    float* orow = iou_out + (((size_t)b * A_NUM + a) * HW + pBase) * NBOX;

    // incremental grid coords
    float fx = (float)(pBase % WW) + 0.5f;
    float fy = (float)(pBase / WW) + 0.5f;

    #pragma unroll
    for (int q = 0; q < 16; q++) {
        float tx = o1[q];
        float ty = o2[q];
        float tw = o3[q];
        float th = o4[q];
        float cx = fx + tx;
        float cy = fy + ty;
        // advance grid coords for next pixel
        fx += 1.f;
        if (fx > (float)WW) { fx = 0.5f; fy += 1.f; }

        float nw = wa * __expf(tw);
        float nh = ha * __expf(th);
        float px1 = cx - nw * 0.5f, px2 = cx + nw * 0.5f;
        float py1 = cy - nh * 0.5f, py2 = cy + nh * 0.5f;
        float parea = (px2 - px1) * (py2 - py1);

        {
            float ix1 = fmaxf(px1, bx0.x);
            float iy1 = fmaxf(py1, bx0.y);
            float ix2 = fminf(px2, bx0.z);
            float iy2 = fminf(py2, bx0.w);
            float inter = fmaxf(ix2 - ix1, 0.f) * fmaxf(iy2 - iy1, 0.f);
            orow[lane] = __fdividef(inter, ga0 + parea - inter);
        }
        {
            float ix1 = fmaxf(px1, bx1.x);
            float iy1 = fmaxf(py1, bx1.y);
            float ix2 = fminf(px2, bx1.z);
            float iy2 = fminf(py2, bx1.w);
            float inter = fmaxf(ix2 - ix1, 0.f) * fmaxf(iy2 - iy1, 0.f);
            orow[lane + 32] = __fdividef(inter, ga1 + parea - inter);
        }
        orow += NBOX;
    }
}

// ---------------------------------------------------------------------------
__global__ __launch_bounds__(64)
void loss_part(const int* __restrict__ pos_idx,
               const int* __restrict__ neg_idx,
               const float* __restrict__ gt_off)
{
    __shared__ float red[64];
    const int tid = threadIdx.x;
    const int m   = blockIdx.x * 64 + tid;
    float s = 0.f;
    {
        int idx = pos_idx[m];
        int b   = idx / (A_NUM * HW);
        int rem = idx % (A_NUM * HW);
        int a   = rem / HW;
        int p   = rem % HW;
        const float* o = g_out2 + ((size_t)b * OUTCH + 5 * a) * HW + p;
        float c  = o[0];
        float sc = 1.f / (1.f + expf(-c));
        float d  = sc - 1.f;
        s += 0.5f * d * d;
        #pragma unroll
        for (int k = 0; k < 4; k++) {
            float dd = o[(size_t)(1 + k) * HW] - gt_off[m * 4 + k];
            s += dd * dd;
        }
        int nidx = neg_idx[m];
        int nb   = nidx / (A_NUM * HW);
        int nrem = nidx % (A_NUM * HW);
        int na   = nrem / HW;
        int np   = nrem % HW;
        float nc = g_out2[((size_t)nb * OUTCH + 5 * na) * HW + np];
        float nsc = 1.f / (1.f + expf(-nc));
        s += 0.5f * nsc * nsc;
    }
    red[tid] = s;
    __syncthreads();
    for (int st = 32; st > 0; st >>= 1) {
        if (tid < st) red[tid] += red[tid + st];
        __syncthreads();
    }
    if (tid == 0) g_loss_part[blockIdx.x] = red[0];
}

__global__ void loss_final(float* __restrict__ out0)
{
    float s = 0.f;
    #pragma unroll
    for (int i = 0; i < 32; i++) s += g_loss_part[i];
    out0[0] = s / (float)MPOS;
}

// ---------------------------------------------------------------------------
__global__ __launch_bounds__(256)
void class_kernel(const int* __restrict__ pos_idx,
                  float* __restrict__ out_cls)
{
    int t = blockIdx.x * blockDim.x + threadIdx.x;
    if (t >= MPOS * C_NUM) return;
    int m = t / C_NUM;
    int c = t % C_NUM;
    int idx = pos_idx[m];
    int b = idx / (A_NUM * HW);
    int p = idx % HW;
    out_cls[t] = g_out2[((size_t)b * OUTCH + 5 * A_NUM + c) * HW + p];
}

// ---------------------------------------------------------------------------
extern "C" void kernel_launch(void* const* d_in, const int* in_sizes, int n_in,
                              void* d_out, int out_size)
{
    const float* features = (const float*)d_in[0];
    const float* w1       = (const float*)d_in[1];
    const float* b1       = (const float*)d_in[2];
    const float* w2       = (const float*)d_in[3];
    const float* b2       = (const float*)d_in[4];
    const float* anc      = (const float*)d_in[5];
    const float* bboxes   = (const float*)d_in[7];
    const float* gt_off   = (const float*)d_in[8];
    const int*   pos_idx  = (const int*)d_in[9];
    const int*   neg_idx  = (const int*)d_in[10];

    float* out      = (float*)d_out;
    float* loss_out = out;
    float* iou_out  = out + 1;
    float* cls_out  = out + 1 + (size_t)BATCH * A_NUM * HW * NBOX;

    cudaFuncSetAttribute(gemm_fused,
                         cudaFuncAttributeMaxDynamicSharedMemorySize, GEMM_SMEM);

    __nv_bfloat16 *w1h, *w1l, *w2h, *w2l;
    cudaGetSymbolAddress((void**)&w1h, g_w1_hi);
    cudaGetSymbolAddress((void**)&w1l, g_w1_lo);
    cudaGetSymbolAddress((void**)&w2h, g_w2_hi);
    cudaGetSymbolAddress((void**)&w2l, g_w2_lo);

    convert_split<<<(KDIM * KDIM / 4 + 255) / 256, 256>>>(w1, w1h, w1l, KDIM * KDIM / 4);
    convert_split<<<(OUTCH * KDIM / 4 + 255) / 256, 256>>>(w2, w2h, w2l, OUTCH * KDIM / 4);

    gemm_fused<<<dim3(49, 1, BATCH), 256, GEMM_SMEM>>>(w1h, w1l, features, b1,
                                                       w2h, w2l, b2);

    head_kernel<<<dim3(25, A_NUM, BATCH), 256>>>(anc, bboxes, iou_out);
    loss_part<<<32, 64>>>(pos_idx, neg_idx, gt_off);
    loss_final<<<1, 1>>>(loss_out);
    class_kernel<<<(MPOS * C_NUM + 255) / 256, 256>>>(pos_idx, cls_out);
}

// round 17
// speedup vs baseline: 1.0725x; 1.0018x over previous
#include <cuda_runtime.h>
#include <cuda_bf16.h>
#include <math.h>
#include <stdint.h>

#define A_NUM   9
#define C_NUM   20
#define OUTCH   65
#define BATCH   32
#define KDIM    256
#define HH      56
#define WW      56
#define HW      3136
#define NBOX    64
#define MPOS    2048

// ---- global scratch ----
__device__ __nv_bfloat16 g_w1_hi[KDIM * KDIM];
__device__ __nv_bfloat16 g_w1_lo[KDIM * KDIM];
__device__ __nv_bfloat16 g_w2_hi[OUTCH * KDIM];
__device__ __nv_bfloat16 g_w2_lo[OUTCH * KDIM];
__device__ float         g_out2 [(size_t)BATCH * OUTCH * HW];   // [b][m][p]
__device__ float         g_loss_part[32];

// ---- helpers ----
__device__ __forceinline__ uint32_t smem_u32(const void* p) {
    uint32_t a;
    asm("{ .reg .u64 t; cvta.to.shared.u64 t, %1; cvt.u32.u64 %0, t; }"
        : "=r"(a) : "l"(p));
    return a;
}
__device__ __forceinline__ uint32_t pk2(__nv_bfloat16 a, __nv_bfloat16 b) {
    __nv_bfloat162 t; t.x = a; t.y = b;
    return *(uint32_t*)&t;
}
__device__ __forceinline__ void split1(float x, __nv_bfloat16& h, __nv_bfloat16& l) {
    h = __float2bfloat16(x);
    l = __float2bfloat16(x - __bfloat162float(h));
}
__device__ __forceinline__ void mma16816(float* c,
    const uint32_t* a, uint32_t b0, uint32_t b1)
{
    asm volatile(
        "mma.sync.aligned.m16n8k16.row.col.f32.bf16.bf16.f32 "
        "{%0,%1,%2,%3}, {%4,%5,%6,%7}, {%8,%9}, {%0,%1,%2,%3};"
        : "+f"(c[0]), "+f"(c[1]), "+f"(c[2]), "+f"(c[3])
        : "r"(a[0]), "r"(a[1]), "r"(a[2]), "r"(a[3]), "r"(b0), "r"(b1));
}
__device__ __forceinline__ void ldmx4(uint32_t* r, uint32_t addr) {
    asm volatile("ldmatrix.sync.aligned.m8n8.x4.shared.b16 {%0,%1,%2,%3}, [%4];"
        : "=r"(r[0]), "=r"(r[1]), "=r"(r[2]), "=r"(r[3]) : "r"(addr));
}
__device__ __forceinline__ void ldmx4t(uint32_t* r, uint32_t addr) {
    asm volatile("ldmatrix.sync.aligned.m8n8.x4.trans.shared.b16 {%0,%1,%2,%3}, [%4];"
        : "=r"(r[0]), "=r"(r[1]), "=r"(r[2]), "=r"(r[3]) : "r"(addr));
}
__device__ __forceinline__ void cpa16(uint32_t dst, const void* src, bool ok) {
    uint32_t sz = ok ? 16u : 0u;
    asm volatile("cp.async.cg.shared.global [%0], [%1], 16, %2;"
                 :: "r"(dst), "l"(src), "r"(sz));
}
__device__ __forceinline__ void cpa_commit() {
    asm volatile("cp.async.commit_group;" ::: "memory");
}
__device__ __forceinline__ void cpa_wait1() {
    asm volatile("cp.async.wait_group 1;" ::: "memory");
}
__device__ __forceinline__ void cpa_wait0() {
    asm volatile("cp.async.wait_group 0;" ::: "memory");
}

// ---- SMEM layout ----
#define APITCH    80
#define BPITCH    144
#define ST_STRIDE 49152
#define AHI_OFF   0
#define ALO_OFF   20480
#define BF32_OFF  40960
#define BHI_OFF   98304
#define BLO_OFF   102912
#define HIDHI     0
#define HIDLO     36864
#define W2BASE    73728
#define W2STG     12800
#define GEMM_SMEM 107520     // 2 CTAs/SM (210KB of 228KB)

// ---------------------------------------------------------------------------
__global__ __launch_bounds__(256)
void convert_split(const float* __restrict__ src,
                   __nv_bfloat16* __restrict__ hi,
                   __nv_bfloat16* __restrict__ lo, int n4)
{
    int t = blockIdx.x * blockDim.x + threadIdx.x;
    if (t >= n4) return;
    float4 v = ((const float4*)src)[t];
    __nv_bfloat16 h0, h1, h2, h3, l0, l1, l2, l3;
    split1(v.x, h0, l0); split1(v.y, h1, l1);
    split1(v.z, h2, l2); split1(v.w, h3, l3);
    ((uint2*)hi)[t] = make_uint2(pk2(h0, h1), pk2(h2, h3));
    ((uint2*)lo)[t] = make_uint2(pk2(l0, l1), pk2(l2, l3));
}

// ---------------------------------------------------------------------------
// Fused conv1+conv2 (unchanged from R13-winning version).
// ---------------------------------------------------------------------------
__global__ __launch_bounds__(256, 2)
void gemm_fused(const __nv_bfloat16* __restrict__ Ahi_g,
                const __nv_bfloat16* __restrict__ Alo_g,
                const float* __restrict__ Fraw,
                const float* __restrict__ bias1,
                const __nv_bfloat16* __restrict__ W2hi_g,
                const __nv_bfloat16* __restrict__ W2lo_g,
                const float* __restrict__ bias2)
{
    extern __shared__ char smem[];
    const uint32_t sb = smem_u32(smem);

    const int b     = blockIdx.z;
    const int nBase = blockIdx.x * 64;
    const int tid   = threadIdx.x;
    const int wid   = tid >> 5;
    const int lane  = tid & 31;
    const int wm    = wid >> 1;
    const int wn    = wid & 1;

    const float* fB = Fraw + (size_t)b * KDIM * HW;

    int aOff[4], aDst[4];
    #pragma unroll
    for (int q = 0; q < 4; q++) {
        int e = tid + q * 256, row = e >> 2, c = e & 3;
        aOff[q] = row * KDIM + c * 8;
        aDst[q] = row * APITCH + c * 16;
    }
    int fDst[2];
    size_t fOff[2];
    #pragma unroll
    for (int q = 0; q < 2; q++) {
        int e = tid + q * 256, row = e >> 4, c4 = e & 15;
        fOff[q] = (size_t)row * HW + nBase + c4 * 4;
        fDst[q] = row * 256 + c4 * 16;
    }

    float acc[4][4][4];
    #pragma unroll
    for (int i = 0; i < 4; i++)
        #pragma unroll
        for (int j = 0; j < 4; j++)
            #pragma unroll
            for (int q = 0; q < 4; q++) acc[i][j][q] = 0.f;

    #define ISSUE1(ST, KO)                                                       \
        do {                                                                     \
            _Pragma("unroll")                                                    \
            for (int q = 0; q < 4; q++) {                                        \
                cpa16((ST) + AHI_OFF + aDst[q], Ahi_g + aOff[q] + (KO), true);   \
                cpa16((ST) + ALO_OFF + aDst[q], Alo_g + aOff[q] + (KO), true);   \
            }                                                                    \
            _Pragma("unroll")                                                    \
            for (int q = 0; q < 2; q++)                                          \
                cpa16((ST) + BF32_OFF + fDst[q],                                 \
                      fB + fOff[q] + (size_t)(KO) * HW, true);                   \
        } while (0)

    ISSUE1(sb, 0);
    cpa_commit();
    ISSUE1(sb + ST_STRIDE, 32);
    cpa_commit();

    const int lane15 = lane & 15;
    const int laneHi = lane >> 4;
    const int kB     = (lane >> 3) & 1;
    const int lane7  = lane & 7;
    const uint32_t aFragBase = (wm * 64 + lane15) * APITCH + laneHi * 16;
    const uint32_t bFragRow  = kB * 8 + lane7;
    const uint32_t bFragCol  = (wn * 32 + laneHi * 8) * 2;

    #pragma unroll 1
    for (int c = 0; c < 8; c++) {
        cpa_wait1();
        __syncthreads();
        const uint32_t st = sb + (c & 1) * ST_STRIDE;

        #pragma unroll
        for (int q = 0; q < 2; q++) {
            int e = tid + q * 256, row = e >> 4, c4 = e & 15;
            float4 v = *(const float4*)(smem + (c & 1) * ST_STRIDE + BF32_OFF
                                        + row * 256 + c4 * 16);
            __nv_bfloat16 h0, h1, h2, h3, l0, l1, l2, l3;
            split1(v.x, h0, l0); split1(v.y, h1, l1);
            split1(v.z, h2, l2); split1(v.w, h3, l3);
            *(uint2*)(smem + BHI_OFF + row * BPITCH + c4 * 8) =
                make_uint2(pk2(h0, h1), pk2(h2, h3));
            *(uint2*)(smem + BLO_OFF + row * BPITCH + c4 * 8) =
                make_uint2(pk2(l0, l1), pk2(l2, l3));
        }
        __syncthreads();

        #pragma unroll
        for (int ks = 0; ks < 2; ks++) {
            uint32_t ah[4][4], bh[4][2];
            #pragma unroll
            for (int i = 0; i < 4; i++)
                ldmx4(ah[i], st + AHI_OFF + aFragBase + i * 16 * APITCH + ks * 32);
            {
                uint32_t r[4];
                ldmx4t(r, sb + BHI_OFF + (ks * 16 + bFragRow) * BPITCH + bFragCol);
                bh[0][0] = r[0]; bh[0][1] = r[1]; bh[1][0] = r[2]; bh[1][1] = r[3];
                ldmx4t(r, sb + BHI_OFF + (ks * 16 + bFragRow) * BPITCH + bFragCol + 32);
                bh[2][0] = r[0]; bh[2][1] = r[1]; bh[3][0] = r[2]; bh[3][1] = r[3];
            }
            #pragma unroll
            for (int i = 0; i < 4; i++)
                #pragma unroll
                for (int j = 0; j < 4; j++)
                    mma16816(acc[i][j], ah[i], bh[j][0], bh[j][1]);
            {
                uint32_t bl[4][2], r[4];
                ldmx4t(r, sb + BLO_OFF + (ks * 16 + bFragRow) * BPITCH + bFragCol);
                bl[0][0] = r[0]; bl[0][1] = r[1]; bl[1][0] = r[2]; bl[1][1] = r[3];
                ldmx4t(r, sb + BLO_OFF + (ks * 16 + bFragRow) * BPITCH + bFragCol + 32);
                bl[2][0] = r[0]; bl[2][1] = r[1]; bl[3][0] = r[2]; bl[3][1] = r[3];
                #pragma unroll
                for (int i = 0; i < 4; i++)
                    #pragma unroll
                    for (int j = 0; j < 4; j++)
                        mma16816(acc[i][j], ah[i], bl[j][0], bl[j][1]);
            }
            {
                uint32_t al[4];
                #pragma unroll
                for (int i = 0; i < 4; i++) {
                    ldmx4(al, st + ALO_OFF + aFragBase + i * 16 * APITCH + ks * 32);
                    #pragma unroll
                    for (int j = 0; j < 4; j++)
                        mma16816(acc[i][j], al, bh[j][0], bh[j][1]);
                }
            }
        }
        __syncthreads();
        if (c + 2 < 8) ISSUE1(sb + (c & 1) * ST_STRIDE, (c + 2) * 32);
        cpa_commit();
    }
    #undef ISSUE1

    cpa_wait0();
    __syncthreads();

    const int w2r0 = tid >> 2, w2c0 = tid & 3;
    const int w2r1 = 64 + (tid >> 2), w2c1 = tid & 3;
    const bool w2a1 = tid < 64;
    const bool w2ok1 = w2a1 && (w2r1 < OUTCH);
    const int w2Off0 = w2r0 * KDIM + w2c0 * 8;
    const int w2Off1 = w2ok1 ? (w2r1 * KDIM + w2c1 * 8) : 0;
    const uint32_t w2Dst0 = w2r0 * 80 + w2c0 * 16;
    const uint32_t w2Dst1 = w2r1 * 80 + w2c1 * 16;

    #define ISSUE2(ST, KO)                                                       \
        do {                                                                     \
            cpa16((ST) + w2Dst0,        W2hi_g + w2Off0 + (KO), true);           \
            cpa16((ST) + 6400 + w2Dst0, W2lo_g + w2Off0 + (KO), true);           \
            if (w2a1) {                                                          \
                cpa16((ST) + w2Dst1,        W2hi_g + w2Off1 + (KO), w2ok1);      \
                cpa16((ST) + 6400 + w2Dst1, W2lo_g + w2Off1 + (KO), w2ok1);      \
            }                                                                    \
        } while (0)

    ISSUE2(sb + W2BASE, 0);
    cpa_commit();
    ISSUE2(sb + W2BASE + W2STG, 32);
    cpa_commit();

    const int g   = lane >> 2;
    const int tig = lane & 3;
    #pragma unroll
    for (int i = 0; i < 4; i++) {
        const int m0 = wm * 64 + i * 16 + g;
        const float bv0 = bias1[m0];
        const float bv1 = bias1[m0 + 8];
        #pragma unroll
        for (int j = 0; j < 4; j++) {
            const int p = wn * 32 + j * 8 + tig * 2;
            float f0 = acc[i][j][0] + bv0; f0 = f0 >= 0.f ? f0 : 0.01f * f0;
            float f1 = acc[i][j][1] + bv0; f1 = f1 >= 0.f ? f1 : 0.01f * f1;
            float f2 = acc[i][j][2] + bv1; f2 = f2 >= 0.f ? f2 : 0.01f * f2;
            float f3 = acc[i][j][3] + bv1; f3 = f3 >= 0.f ? f3 : 0.01f * f3;
            __nv_bfloat16 h0, h1, h2, h3, l0, l1, l2, l3;
            split1(f0, h0, l0); split1(f1, h1, l1);
            split1(f2, h2, l2); split1(f3, h3, l3);
            *(uint32_t*)(smem + HIDHI + m0 * BPITCH + p * 2)       = pk2(h0, h1);
            *(uint32_t*)(smem + HIDLO + m0 * BPITCH + p * 2)       = pk2(l0, l1);
            *(uint32_t*)(smem + HIDHI + (m0 + 8) * BPITCH + p * 2) = pk2(h2, h3);
            *(uint32_t*)(smem + HIDLO + (m0 + 8) * BPITCH + p * 2) = pk2(l2, l3);
        }
    }
    __syncthreads();

    const int mw = wid >> 1;
    const int nw = wid & 1;
    const int ibase = (mw == 0) ? 0 : (mw + 1);
    const int icnt  = (mw == 0) ? 2 : 1;

    float acc2[2][4][4];
    #pragma unroll
    for (int ii = 0; ii < 2; ii++)
        #pragma unroll
        for (int j = 0; j < 4; j++)
            #pragma unroll
            for (int q = 0; q < 4; q++) acc2[ii][j][q] = 0.f;

    const uint32_t a2Frag = lane15 * 80 + laneHi * 16;
    const uint32_t b2Col  = (nw * 32 + laneHi * 8) * 2;

    #pragma unroll 1
    for (int c = 0; c < 8; c++) {
        cpa_wait1();
        __syncthreads();
        const uint32_t st = sb + W2BASE + (c & 1) * W2STG;

        #pragma unroll
        for (int ks = 0; ks < 2; ks++) {
            const uint32_t hidRow = (c * 32 + ks * 16 + bFragRow) * BPITCH + b2Col;
            uint32_t bh[4][2], bl[4][2], r[4];
            ldmx4t(r, sb + HIDHI + hidRow);
            bh[0][0] = r[0]; bh[0][1] = r[1]; bh[1][0] = r[2]; bh[1][1] = r[3];
            ldmx4t(r, sb + HIDHI + hidRow + 32);
            bh[2][0] = r[0]; bh[2][1] = r[1]; bh[3][0] = r[2]; bh[3][1] = r[3];
            ldmx4t(r, sb + HIDLO + hidRow);
            bl[0][0] = r[0]; bl[0][1] = r[1]; bl[1][0] = r[2]; bl[1][1] = r[3];
            ldmx4t(r, sb + HIDLO + hidRow + 32);
            bl[2][0] = r[0]; bl[2][1] = r[1]; bl[3][0] = r[2]; bl[3][1] = r[3];

            #pragma unroll
            for (int ii = 0; ii < 2; ii++) {
                if (ii < icnt) {
                    const int i = ibase + ii;
                    uint32_t ah[4], al[4];
                    ldmx4(ah, st + a2Frag + i * 16 * 80 + ks * 32);
                    ldmx4(al, st + 6400 + a2Frag + i * 16 * 80 + ks * 32);
                    #pragma unroll
                    for (int j = 0; j < 4; j++) {
                        mma16816(acc2[ii][j], ah, bh[j][0], bh[j][1]);
                        mma16816(acc2[ii][j], ah, bl[j][0], bl[j][1]);
                        mma16816(acc2[ii][j], al, bh[j][0], bh[j][1]);
                    }
                }
            }
        }
        __syncthreads();
        if (c + 2 < 8) ISSUE2(sb + W2BASE + (c & 1) * W2STG, (c + 2) * 32);
        cpa_commit();
    }
    #undef ISSUE2

    #pragma unroll
    for (int ii = 0; ii < 2; ii++) {
        if (ii < icnt) {
            const int i = ibase + ii;
            const int m0 = i * 16 + g;
            const int m1 = m0 + 8;
            #pragma unroll
            for (int j = 0; j < 4; j++) {
                const int p = nBase + nw * 32 + j * 8 + tig * 2;
                if (m0 < OUTCH) {
                    const float bv = bias2[m0];
                    float2 v = make_float2(acc2[ii][j][0] + bv, acc2[ii][j][1] + bv);
                    *(float2*)&g_out2[((size_t)b * OUTCH + m0) * HW + p] = v;
                }
                if (m1 < OUTCH) {
                    const float bv = bias2[m1];
                    float2 v = make_float2(acc2[ii][j][2] + bv, acc2[ii][j][3] + bv);
                    *(float2*)&g_out2[((size_t)b * OUTCH + m1) * HW + p] = v;
                }
            }
        }
    }
}

// ---------------------------------------------------------------------------
// Head: register-hoisted boxes, incremental addressing, guard-free 16-pixel
// strips (HW = 196*16 exactly -> a warp strip is fully valid or fully idle).
// ---------------------------------------------------------------------------
__global__ __launch_bounds__(256)
void head_kernel(const float* __restrict__ anc,
                 const float* __restrict__ bboxes,
                 float* __restrict__ iou_out)
{
    __shared__ float4 box[NBOX];
    __shared__ float  gar[NBOX];
    const int b = blockIdx.z;
    const int a = blockIdx.y;
    const int tid  = threadIdx.x;
    const int wid  = tid >> 5;
    const int lane = tid & 31;

    if (tid < NBOX) {
        const float* bb = bboxes + ((size_t)b * NBOX + tid) * 5;
        float x1 = bb[0], y1 = bb[1], x2 = bb[2], y2 = bb[3];
        box[tid] = make_float4(x1, y1, x2, y2);
        gar[tid] = (x2 - x1) * (y2 - y1);
    }
    __syncthreads();

    const int pBase = blockIdx.x * 128 + wid * 16;
    if (pBase >= HW) return;                 // whole strip out of range

    // hoist this thread's two boxes into registers (invariant over pixels)
    const float4 bx0 = box[lane];
    const float4 bx1 = box[lane + 32];
    const float  ga0 = gar[lane];
    const float  ga1 = gar[lane + 32];

    const float wa = anc[a * 2 + 0], ha = anc[a * 2 + 1];
    const float* o1 = g_out2 + ((size_t)b * OUTCH + 5 * a + 1) * HW + pBase;
    const float* o2 = o1 + HW;
    const float* o3 = o2 + HW;
    const float* o4 = o3 + HW;
    float* orow = iou_out + (((size_t)b * A_NUM + a) * HW + pBase) * NBOX;

    // incremental grid coords
    float fx = (float)(pBase % WW) + 0.5f;
    float fy = (float)(pBase / WW) + 0.5f;

    #pragma unroll
    for (int q = 0; q < 16; q++) {
        float tx = o1[q];
        float ty = o2[q];
        float tw = o3[q];
        float th = o4[q];
        float cx = fx + tx;
        float cy = fy + ty;
        // advance grid coords for next pixel
        fx += 1.f;
        if (fx > (float)WW) { fx = 0.5f; fy += 1.f; }

        float nw = wa * __expf(tw);
        float nh = ha * __expf(th);
        float px1 = cx - nw * 0.5f, px2 = cx + nw * 0.5f;
        float py1 = cy - nh * 0.5f, py2 = cy + nh * 0.5f;
        float parea = (px2 - px1) * (py2 - py1);

        {
            float ix1 = fmaxf(px1, bx0.x);
            float iy1 = fmaxf(py1, bx0.y);
            float ix2 = fminf(px2, bx0.z);
            float iy2 = fminf(py2, bx0.w);
            float inter = fmaxf(ix2 - ix1, 0.f) * fmaxf(iy2 - iy1, 0.f);
            orow[lane] = __fdividef(inter, ga0 + parea - inter);
        }
        {
            float ix1 = fmaxf(px1, bx1.x);
            float iy1 = fmaxf(py1, bx1.y);
            float ix2 = fminf(px2, bx1.z);
            float iy2 = fminf(py2, bx1.w);
            float inter = fmaxf(ix2 - ix1, 0.f) * fmaxf(iy2 - iy1, 0.f);
            orow[lane + 32] = __fdividef(inter, ga1 + parea - inter);
        }
        orow += NBOX;
    }
}

// ---------------------------------------------------------------------------
__global__ __launch_bounds__(64)
void loss_part(const int* __restrict__ pos_idx,
               const int* __restrict__ neg_idx,
               const float* __restrict__ gt_off)
{
    __shared__ float red[64];
    const int tid = threadIdx.x;
    const int m   = blockIdx.x * 64 + tid;
    float s = 0.f;
    {
        int idx = pos_idx[m];
        int b   = idx / (A_NUM * HW);
        int rem = idx % (A_NUM * HW);
        int a   = rem / HW;
        int p   = rem % HW;
        const float* o = g_out2 + ((size_t)b * OUTCH + 5 * a) * HW + p;
        float c  = o[0];
        float sc = 1.f / (1.f + expf(-c));
        float d  = sc - 1.f;
        s += 0.5f * d * d;
        #pragma unroll
        for (int k = 0; k < 4; k++) {
            float dd = o[(size_t)(1 + k) * HW] - gt_off[m * 4 + k];
            s += dd * dd;
        }
        int nidx = neg_idx[m];
        int nb   = nidx / (A_NUM * HW);
        int nrem = nidx % (A_NUM * HW);
        int na   = nrem / HW;
        int np   = nrem % HW;
        float nc = g_out2[((size_t)nb * OUTCH + 5 * na) * HW + np];
        float nsc = 1.f / (1.f + expf(-nc));
        s += 0.5f * nsc * nsc;
    }
    red[tid] = s;
    __syncthreads();
    for (int st = 32; st > 0; st >>= 1) {
        if (tid < st) red[tid] += red[tid + st];
        __syncthreads();
    }
    if (tid == 0) g_loss_part[blockIdx.x] = red[0];
}

__global__ void loss_final(float* __restrict__ out0)
{
    float s = 0.f;
    #pragma unroll
    for (int i = 0; i < 32; i++) s += g_loss_part[i];
    out0[0] = s / (float)MPOS;
}

// ---------------------------------------------------------------------------
__global__ __launch_bounds__(256)
void class_kernel(const int* __restrict__ pos_idx,
                  float* __restrict__ out_cls)
{
    int t = blockIdx.x * blockDim.x + threadIdx.x;
    if (t >= MPOS * C_NUM) return;
    int m = t / C_NUM;
    int c = t % C_NUM;
    int idx = pos_idx[m];
    int b = idx / (A_NUM * HW);
    int p = idx % HW;
    out_cls[t] = g_out2[((size_t)b * OUTCH + 5 * A_NUM + c) * HW + p];
}

// ---------------------------------------------------------------------------
extern "C" void kernel_launch(void* const* d_in, const int* in_sizes, int n_in,
                              void* d_out, int out_size)
{
    const float* features = (const float*)d_in[0];
    const float* w1       = (const float*)d_in[1];
    const float* b1       = (const float*)d_in[2];
    const float* w2       = (const float*)d_in[3];
    const float* b2       = (const float*)d_in[4];
    const float* anc      = (const float*)d_in[5];
    const float* bboxes   = (const float*)d_in[7];
    const float* gt_off   = (const float*)d_in[8];
    const int*   pos_idx  = (const int*)d_in[9];
    const int*   neg_idx  = (const int*)d_in[10];

    float* out      = (float*)d_out;
    float* loss_out = out;
    float* iou_out  = out + 1;
    float* cls_out  = out + 1 + (size_t)BATCH * A_NUM * HW * NBOX;

    cudaFuncSetAttribute(gemm_fused,
                         cudaFuncAttributeMaxDynamicSharedMemorySize, GEMM_SMEM);

    __nv_bfloat16 *w1h, *w1l, *w2h, *w2l;
    cudaGetSymbolAddress((void**)&w1h, g_w1_hi);
    cudaGetSymbolAddress((void**)&w1l, g_w1_lo);
    cudaGetSymbolAddress((void**)&w2h, g_w2_hi);
    cudaGetSymbolAddress((void**)&w2l, g_w2_lo);

    convert_split<<<(KDIM * KDIM / 4 + 255) / 256, 256>>>(w1, w1h, w1l, KDIM * KDIM / 4);
    convert_split<<<(OUTCH * KDIM / 4 + 255) / 256, 256>>>(w2, w2h, w2l, OUTCH * KDIM / 4);

    gemm_fused<<<dim3(49, 1, BATCH), 256, GEMM_SMEM>>>(w1h, w1l, features, b1,
                                                       w2h, w2l, b2);

    head_kernel<<<dim3(25, A_NUM, BATCH), 256>>>(anc, bboxes, iou_out);
    loss_part<<<32, 64>>>(pos_idx, neg_idx, gt_off);
    loss_final<<<1, 1>>>(loss_out);
    class_kernel<<<(MPOS * C_NUM + 255) / 256, 256>>>(pos_idx, cls_out);
}